// round 9
// baseline (speedup 1.0000x reference)
#include <cuda_runtime.h>
#include <cstdint>

// Problem constants
#define NB      4
#define NN      2048
#define PP      2096128            // NN*(NN-1)/2
#define TOTALF  (NB*PP)            // 8384512 flat pair slots per output row
#define RPB     8                  // rows per block
#define GBLK    (NB * (NN / RPB))  // 1024 blocks
#define MAXC    64                 // max j-chunks (32 pairs) per row
#define CPBLK   (RPB * MAXC)       // 512 mask slots per block
#define THREADS 256

// d2 <= 25.0f + 1ulp  <=>  sqrtf(d2) <= 5.0f (correctly rounded sqrt)
#define THR_BITS   0x41C80001u
#define NEG1F_BITS 0xBF800000      // -1.0f

// Scratch (no allocations allowed -> __device__ globals)
__device__ unsigned g_mask[GBLK * CPBLK];   // 2 MB validity bitmasks
__device__ int g_bcnt[GBLK];
__device__ int g_boff[GBLK];

// ---------------------------------------------------------------------------
// Pass 1: validity masks (one ballot per (row, 32-j chunk)) + per-block counts
// ---------------------------------------------------------------------------
__global__ void __launch_bounds__(THREADS) count_kernel(const float* __restrict__ x) {
    __shared__ float sx[NN];
    __shared__ float sy[NN];
    __shared__ float sz[NN];
    __shared__ int wsum[8];

    const int g  = blockIdx.x;
    const int b  = g >> 8;              // batch
    const int r0 = (g & 255) * RPB;     // first row of this block
    const float* xb = x + (size_t)b * NN * 3;

    for (int idx = threadIdx.x; idx < NN * 3; idx += THREADS) {
        float v = xb[idx];
        int pt = idx / 3, c = idx - pt * 3;
        if (c == 0) sx[pt] = v; else if (c == 1) sy[pt] = v; else sz[pt] = v;
    }
    __syncthreads();

    const int w    = threadIdx.x >> 5;
    const int lane = threadIdx.x & 31;
    const float thr = __uint_as_float(THR_BITS);

    int cnt = 0;
    #pragma unroll
    for (int r = 0; r < RPB; r++) {
        const int i = r0 + r;
        const float xi = sx[i], yi = sy[i], zi = sz[i];
        const int jcount = NN - 1 - i;
        #pragma unroll
        for (int k = 0; k < 8; k++) {
            const int c = k * 8 + w;            // chunk index 0..63
            int valid = 0;
            if ((c << 5) < jcount) {
                int j = i + 1 + (c << 5) + lane;
                if (j < NN) {
                    float dx = __fsub_rn(xi, sx[j]);
                    float dy = __fsub_rn(yi, sy[j]);
                    float dz = __fsub_rn(zi, sz[j]);
                    float d2 = __fadd_rn(__fadd_rn(__fmul_rn(dx, dx), __fmul_rn(dy, dy)),
                                         __fmul_rn(dz, dz));
                    valid = (d2 <= thr);
                }
            }
            unsigned m = __ballot_sync(0xffffffffu, valid);
            if (lane == 0) g_mask[g * CPBLK + r * MAXC + c] = m;
            cnt += __popc(m);
        }
    }

    if (lane == 0) wsum[w] = cnt;
    __syncthreads();
    if (threadIdx.x == 0) {
        int s = 0;
        #pragma unroll
        for (int ww = 0; ww < 8; ww++) s += wsum[ww];
        g_bcnt[g] = s;
    }
}

// ---------------------------------------------------------------------------
// Pass 2: fill -1.0f everywhere (float32 output), vectorized; scatter
// overwrites the valid prefix afterwards.
// ---------------------------------------------------------------------------
__global__ void __launch_bounds__(256) fill_kernel(int4* __restrict__ out) {
    const int NV = 2 * TOTALF / 4;   // 4,192,256 int4 vectors
    int v = blockIdx.x * 256 + threadIdx.x;
    if (v < NV) {
        int4 m;
        m.x = NEG1F_BITS; m.y = NEG1F_BITS; m.z = NEG1F_BITS; m.w = NEG1F_BITS;
        out[v] = m;
    }
}

// ---------------------------------------------------------------------------
// Pass 3: exclusive scan of 1024 block counts (single block)
// ---------------------------------------------------------------------------
__global__ void __launch_bounds__(1024) scan_kernel() {
    __shared__ int s[1024];
    const int t = threadIdx.x;
    int c = g_bcnt[t];
    s[t] = c;
    __syncthreads();
    for (int d = 1; d < 1024; d <<= 1) {
        int v = (t >= d) ? s[t - d] : 0;
        __syncthreads();
        s[t] += v;
        __syncthreads();
    }
    g_boff[t] = s[t] - c;
}

// ---------------------------------------------------------------------------
// Pass 4: replay masks, ordered write of edges (float32 values)
// ---------------------------------------------------------------------------
__global__ void __launch_bounds__(THREADS) scatter_kernel(float* __restrict__ out0,
                                                          float* __restrict__ out1) {
    __shared__ int ps[CPBLK];     // exclusive prefix of chunk popcounts
    __shared__ int pc2[256];      // pair-sum scan workspace

    const int g  = blockIdx.x;
    const int b  = g >> 8;
    const int r0 = (g & 255) * RPB;
    const int t  = threadIdx.x;
    const unsigned* mblk = &g_mask[g * CPBLK];

    int a0 = __popc(mblk[2 * t]);
    int a1 = __popc(mblk[2 * t + 1]);
    int pair = a0 + a1;
    pc2[t] = pair;
    __syncthreads();
    for (int d = 1; d < 256; d <<= 1) {
        int v = (t >= d) ? pc2[t - d] : 0;
        __syncthreads();
        pc2[t] += v;
        __syncthreads();
    }
    int excl = pc2[t] - pair;
    ps[2 * t]     = excl;
    ps[2 * t + 1] = excl + a0;
    __syncthreads();

    const int base = g_boff[g];
    const int w    = t >> 5;
    const int lane = t & 31;
    const unsigned lt = (1u << lane) - 1u;
    const int bofs = b * NN;

    #pragma unroll
    for (int r = 0; r < RPB; r++) {
        const int i = r0 + r;
        #pragma unroll
        for (int k = 0; k < 8; k++) {
            const int c = k * 8 + w;
            unsigned m = mblk[r * MAXC + c];
            if (m & (1u << lane)) {
                int j = i + 1 + (c << 5) + lane;
                int pos = base + ps[r * MAXC + c] + __popc(m & lt);
                if (pos >= 0 && pos < TOTALF) {   // defensive clamp
                    out0[pos] = (float)(bofs + i);
                    out1[pos] = (float)(bofs + j);
                }
            }
        }
    }
}

extern "C" void kernel_launch(void* const* d_in, const int* in_sizes, int n_in,
                              void* d_out, int out_size) {
    const float* x = (const float*)d_in[0];
    float* out = (float*)d_out;
    (void)in_sizes; (void)n_in; (void)out_size;

    count_kernel<<<GBLK, THREADS>>>(x);
    fill_kernel<<<(2 * TOTALF / 4 + 255) / 256, 256>>>((int4*)out);
    scan_kernel<<<1, 1024>>>();
    scatter_kernel<<<GBLK, THREADS>>>(out, out + TOTALF);
}

// round 10
// speedup vs baseline: 1.0597x; 1.0597x over previous
#include <cuda_runtime.h>
#include <cstdint>

// Problem constants
#define NB      4
#define NN      2048
#define PP      2096128            // NN*(NN-1)/2
#define TOTALF  (NB*PP)            // 8384512 flat pair slots per output row
#define RPB     8                  // rows per block
#define GBLK    (NB * (NN / RPB))  // 1024 blocks
#define MAXC    64                 // max j-chunks (32 pairs) per row
#define CPBLK   (RPB * MAXC)       // 512 mask slots per block
#define THREADS 256
#define FULL    0xffffffffu

// d2 <= 25.0f + 1ulp  <=>  sqrtf(d2) <= 5.0f (correctly rounded sqrt)
#define THR_BITS 0x41C80001u

// decoupled-lookback status word: flag in top bits, count in low 30
#define FLAG_A  0x40000000u
#define FLAG_P  0x80000000u
#define VALM    0x3FFFFFFFu

__device__ unsigned g_status[GBLK];   // zero-init at module load; reset by fill
__device__ int g_total;

// ---------------------------------------------------------------------------
// Fused: count masks (smem-resident) + decoupled-lookback global prefix +
// ordered scatter of valid edges. One kernel, one pass over the pair space.
// ---------------------------------------------------------------------------
__global__ void __launch_bounds__(THREADS) fused_kernel(const float* __restrict__ x,
                                                        float* __restrict__ out0,
                                                        float* __restrict__ out1) {
    __shared__ float sx[NN];
    __shared__ float sy[NN];
    __shared__ float sz[NN];
    __shared__ unsigned smask[CPBLK];
    __shared__ int soff[CPBLK];
    __shared__ int wtot[8];
    __shared__ int wexc[8];
    __shared__ int s_base;
    __shared__ int s_cnt;

    const int g  = blockIdx.x;
    const int b  = g >> 8;
    const int r0 = (g & 255) * RPB;
    const int t  = threadIdx.x;
    const int w  = t >> 5;
    const int lane = t & 31;
    const float* xb = x + (size_t)b * NN * 3;

    for (int idx = t; idx < NN * 3; idx += THREADS) {
        float v = xb[idx];
        int pt = idx / 3, c3 = idx - pt * 3;
        if (c3 == 0) sx[pt] = v; else if (c3 == 1) sy[pt] = v; else sz[pt] = v;
    }
    smask[2 * t]     = 0;
    smask[2 * t + 1] = 0;
    __syncthreads();

    // ---- count: ballots into smem, triangular chunk loop (active chunks only)
    const float thr = __uint_as_float(THR_BITS);
    #pragma unroll
    for (int r = 0; r < RPB; r++) {
        const int i = r0 + r;
        const float xi = sx[i], yi = sy[i], zi = sz[i];
        const int nch = (NN - 1 - i + 31) >> 5;   // active 32-wide chunks this row
        for (int c = w; c < nch; c += 8) {
            int j = i + 1 + (c << 5) + lane;
            int valid = 0;
            if (j < NN) {
                float dx = __fsub_rn(xi, sx[j]);
                float dy = __fsub_rn(yi, sy[j]);
                float dz = __fsub_rn(zi, sz[j]);
                float d2 = __fadd_rn(__fadd_rn(__fmul_rn(dx, dx), __fmul_rn(dy, dy)),
                                     __fmul_rn(dz, dz));
                valid = (d2 <= thr);
            }
            unsigned m = __ballot_sync(FULL, valid);
            if (lane == 0) smask[r * MAXC + c] = m;
        }
    }
    __syncthreads();

    // ---- block scan over 512 chunk popcounts (2 per thread, shfl-based)
    unsigned m0 = smask[2 * t], m1 = smask[2 * t + 1];
    int p0 = __popc(m0);
    int p  = p0 + __popc(m1);
    int inc = p;
    #pragma unroll
    for (int d = 1; d < 32; d <<= 1) {
        int v = __shfl_up_sync(FULL, inc, d);
        if (lane >= d) inc += v;
    }
    if (lane == 31) wtot[w] = inc;
    __syncthreads();
    if (t < 32) {
        int vw = (lane < 8) ? wtot[lane] : 0;
        int winc = vw;
        #pragma unroll
        for (int d = 1; d < 8; d <<= 1) {
            int v = __shfl_up_sync(FULL, winc, d);
            if (lane >= d) winc += v;
        }
        if (lane < 8) wexc[lane] = winc - vw;
        if (lane == 7) s_cnt = winc;
    }
    __syncthreads();
    int e0 = wexc[w] + (inc - p);
    soff[2 * t]     = e0;
    soff[2 * t + 1] = e0 + p0;

    // ---- decoupled lookback (warp 0): global exclusive prefix of block counts
    if (w == 0) {
        const int cnt = s_cnt;
        if (g == 0) {
            if (lane == 0) {
                atomicExch(&g_status[0], FLAG_P | (unsigned)cnt);
                s_base = 0;
            }
        } else {
            if (lane == 0) atomicExch(&g_status[g], FLAG_A | (unsigned)cnt);
            int excl = 0;
            int idx = g - 1;
            while (true) {
                int k = idx - lane;
                unsigned s = 0;
                if (k >= 0) {
                    volatile unsigned* ptr = (volatile unsigned*)&g_status[k];
                    do { s = *ptr; } while (s == 0);
                }
                unsigned pf = __ballot_sync(FULL, (s & FLAG_P) != 0);
                if (pf) {
                    int fp = __ffs(pf) - 1;   // nearest predecessor with full prefix
                    int contrib = (lane <= fp) ? (int)(s & VALM) : 0;
                    excl += __reduce_add_sync(FULL, contrib);
                    break;
                } else {
                    excl += __reduce_add_sync(FULL, (int)(s & VALM));
                    idx -= 32;
                }
            }
            if (lane == 0) {
                atomicExch(&g_status[g], FLAG_P | (unsigned)(excl + cnt));
                s_base = excl;
                if (g == GBLK - 1) g_total = excl + cnt;
            }
        }
    }
    __syncthreads();

    // ---- ordered scatter straight from smem masks
    const int base = s_base;
    const unsigned lt = (1u << lane) - 1u;
    const int bofs = b * NN;

    #pragma unroll
    for (int r = 0; r < RPB; r++) {
        const int i = r0 + r;
        const int nch = (NN - 1 - i + 31) >> 5;
        for (int c = w; c < nch; c += 8) {
            unsigned m = smask[r * MAXC + c];
            if (m & (1u << lane)) {
                int j = i + 1 + (c << 5) + lane;
                int pos = base + soff[r * MAXC + c] + __popc(m & lt);
                out0[pos] = (float)(bofs + i);
                out1[pos] = (float)(bofs + j);
            }
        }
    }
}

// ---------------------------------------------------------------------------
// Fill -1.0f into the invalid tail [total, TOTALF) of both rows (vectorized),
// and reset lookback statuses for the next graph replay.
// ---------------------------------------------------------------------------
__global__ void __launch_bounds__(256) fill_kernel(float* __restrict__ out) {
    const int total = g_total;
    const int gt = blockIdx.x * 256 + threadIdx.x;
    if (gt < GBLK) g_status[gt] = 0;          // reset for next replay
    const int NV = 2 * TOTALF / 4;            // TOTALF % 4 == 0: no row straddle
    if (gt >= NV) return;
    const int q0 = gt * 4;
    const int local = (q0 < TOTALF) ? q0 : q0 - TOTALF;  // row-local element idx
    if (local >= total) {
        int4 mm;
        mm.x = mm.y = mm.z = mm.w = 0xBF800000;   // -1.0f x4
        reinterpret_cast<int4*>(out)[gt] = mm;
    } else if (local + 4 > total) {
        #pragma unroll
        for (int e = 0; e < 4; e++)
            if (local + e >= total) out[q0 + e] = -1.0f;
    }
}

extern "C" void kernel_launch(void* const* d_in, const int* in_sizes, int n_in,
                              void* d_out, int out_size) {
    const float* x = (const float*)d_in[0];
    float* out = (float*)d_out;
    (void)in_sizes; (void)n_in; (void)out_size;

    fused_kernel<<<GBLK, THREADS>>>(x, out, out + TOTALF);
    fill_kernel<<<(2 * TOTALF / 4 + 255) / 256, 256>>>(out);
}